// round 15
// baseline (speedup 1.0000x reference)
#include <cuda_runtime.h>
#include <cuda_fp16.h>
#include <math.h>
#include <stdint.h>

// ---------------- problem constants ----------------
#define BB      2
#define CC      1024
#define TT      1024
#define TOKS    (BB * TT)          // 2048
#define DIN     2048
#define DSTATE  16
#define DTRANK  64
#define XDBL    96
#define DCONV   4
#define SW      64                 // scan window (t-steps)

// ---------------- fp32 scratch ----------------
__device__ float g_xdbl[TOKS * XDBL];

// ---------------- fp16 scratch ----------------
__device__ __half e_xn [TOKS * CC];
__device__ __half e_w1 [2 * DIN * CC];
__device__ __half e_xz [TOKS * 2 * DIN];
__device__ __half e_xc [TOKS * DIN];
__device__ __half e_w2 [XDBL * DIN];
__device__ __half e_dtr[TOKS * DTRANK];
__device__ __half e_w3 [DIN * DTRANK];
__device__ __half e_y  [TOKS * DIN];
__device__ __half e_w4 [CC * DIN];

// ==================== PTX helpers ====================
__device__ __forceinline__ uint32_t smem_u32(const void* p) {
    uint32_t a;
    asm("{ .reg .u64 t; cvta.to.shared.u64 t, %1; cvt.u32.u64 %0, t; }" : "=r"(a) : "l"(p));
    return a;
}
__device__ __forceinline__ void cp16(uint32_t dst, const void* src, bool pred) {
    int sz = pred ? 16 : 0;
    asm volatile("cp.async.cg.shared.global [%0], [%1], 16, %2;\n" :: "r"(dst), "l"(src), "r"(sz));
}
__device__ __forceinline__ void ldsm4(uint32_t& r0, uint32_t& r1, uint32_t& r2, uint32_t& r3,
                                      uint32_t addr) {
    asm volatile("ldmatrix.sync.aligned.m8n8.x4.shared.b16 {%0,%1,%2,%3}, [%4];"
                 : "=r"(r0), "=r"(r1), "=r"(r2), "=r"(r3) : "r"(addr));
}
__device__ __forceinline__ void mma16816(float* c, const uint32_t* a, const uint32_t* b) {
    asm volatile("mma.sync.aligned.m16n8k16.row.col.f32.f16.f16.f32 "
                 "{%0,%1,%2,%3}, {%4,%5,%6,%7}, {%8,%9}, {%0,%1,%2,%3};"
                 : "+f"(c[0]), "+f"(c[1]), "+f"(c[2]), "+f"(c[3])
                 : "r"(a[0]), "r"(a[1]), "r"(a[2]), "r"(a[3]), "r"(b[0]), "r"(b[1]));
}

// ==================== mma.sync fp16 GEMM ====================
// OP 2: transpose+residual fp32 | OP 4: plain fp16 store
// OP 5: x_proj epilogue: fp32 -> g_xdbl AND fp16 dt_raw -> e_dtr
template <int OP, int NT>
__global__ __launch_bounds__(256, 2)
void gemm_mma(const __half* __restrict__ A, int lda,
              const __half* __restrict__ W, int ldw,
              void* __restrict__ Cout, int ldc,
              int M, int N, int Kext,
              const float* __restrict__ resid) {
    constexpr int SA     = 128 * 128;
    constexpr int SB     = NT * 128;
    constexpr int STAGE  = SA + SB;
    constexpr int WCOLS  = NT / 2;
    constexpr int NFR    = WCOLS / 8;
    constexpr int BLD    = WCOLS / 16;
    constexpr int BCHUNK = NT * 8 / 256;

    extern __shared__ float4 dyn4[];
    uint32_t base = smem_u32(dyn4);

    int tid = threadIdx.x, lane = tid & 31, warp = tid >> 5;
    int wm = warp & 3, wn = warp >> 2;
    int rowBase = blockIdx.y * 128, colBase = blockIdx.x * NT;

    float* Cf = (float*)Cout;
    __half* Ch = (__half*)Cout;

    int nTiles = Kext / 64;

    float acc[2][NFR][4];
#pragma unroll
    for (int i = 0; i < 2; i++)
#pragma unroll
        for (int j = 0; j < NFR; j++)
#pragma unroll
            for (int e = 0; e < 4; e++) acc[i][j][e] = 0.f;

    auto load_tile = [&](int s, int kt) {
        uint32_t aB = base + s * STAGE, bB = aB + SA;
        int k0 = kt * 64;
#pragma unroll
        for (int i = 0; i < 4; i++) {
            int idx = tid + i * 256;
            int row = idx >> 3, c = idx & 7;
            cp16(aB + row * 128 + ((c ^ (row & 7)) << 4),
                 A + (size_t)(rowBase + row) * lda + k0 + c * 8, true);
        }
#pragma unroll
        for (int i = 0; i < BCHUNK; i++) {
            int idx = tid + i * 256;
            int row = idx >> 3, c = idx & 7;
            bool ok = (colBase + row) < N;
            cp16(bB + row * 128 + ((c ^ (row & 7)) << 4),
                 W + (ok ? (size_t)(colBase + row) * ldw : 0) + k0 + c * 8, ok);
        }
        asm volatile("cp.async.commit_group;\n");
    };

    load_tile(0, 0);
    if (nTiles > 1) load_tile(1, 1);

    for (int t = 0; t < nTiles; t++) {
        if (t + 1 >= nTiles) asm volatile("cp.async.wait_group 0;\n");
        else                 asm volatile("cp.async.wait_group 1;\n");
        __syncthreads();

        int s = t % 3;
        uint32_t aB = base + s * STAGE, bB = aB + SA;
#pragma unroll
        for (int ks = 0; ks < 4; ks++) {
            uint32_t afr[2][4];
#pragma unroll
            for (int mt = 0; mt < 2; mt++) {
                int row = wm * 32 + mt * 16 + (lane & 15);
                int unit = ks * 2 + (lane >> 4);
                ldsm4(afr[mt][0], afr[mt][1], afr[mt][2], afr[mt][3],
                      aB + row * 128 + ((unit ^ (row & 7)) << 4));
            }
            uint32_t bfr[NFR][2];
#pragma unroll
            for (int p = 0; p < BLD; p++) {
                int row = wn * WCOLS + p * 16 + (lane & 15);
                int unit = ks * 2 + (lane >> 4);
                uint32_t r0, r1, r2, r3;
                ldsm4(r0, r1, r2, r3, bB + row * 128 + ((unit ^ (row & 7)) << 4));
                bfr[2 * p][0] = r0; bfr[2 * p + 1][0] = r1;
                bfr[2 * p][1] = r2; bfr[2 * p + 1][1] = r3;
            }
#pragma unroll
            for (int mt = 0; mt < 2; mt++)
#pragma unroll
                for (int nt = 0; nt < NFR; nt++)
                    mma16816(acc[mt][nt], afr[mt], bfr[nt]);
        }
        if (t + 2 < nTiles) load_tile((t + 2) % 3, t + 2);
    }

    if (OP == 2) {
        __syncthreads();
        float* st = (float*)dyn4;
        const int PITCH = 132;
#pragma unroll
        for (int mt = 0; mt < 2; mt++)
#pragma unroll
            for (int nt = 0; nt < NFR; nt++)
#pragma unroll
                for (int e = 0; e < 4; e++) {
                    int ml = wm * 32 + mt * 16 + (lane >> 2) + ((e >= 2) ? 8 : 0);
                    int nl = wn * WCOLS + nt * 8 + (lane & 3) * 2 + (e & 1);
                    st[nl * PITCH + ml] = acc[mt][nt][e];
                }
        __syncthreads();
        int b = rowBase >> 10, t0 = rowBase & 1023;
        for (int r = warp; r < 128; r += 8) {
            float4 v = *(float4*)&st[r * PITCH + lane * 4];
            size_t oi = (size_t)b * CC * TT + (size_t)(colBase + r) * TT + t0 + lane * 4;
            float4 rv = *(const float4*)(resid + oi);
            v.x += rv.x; v.y += rv.y; v.z += rv.z; v.w += rv.w;
            *(float4*)(Cf + oi) = v;
        }
    } else if (OP == 5) {
#pragma unroll
        for (int mt = 0; mt < 2; mt++) {
            int m = rowBase + wm * 32 + mt * 16 + (lane >> 2);
#pragma unroll
            for (int nt = 0; nt < NFR; nt++) {
                int c0 = colBase + wn * WCOLS + nt * 8 + (lane & 3) * 2;
#pragma unroll
                for (int e = 0; e < 4; e++) {
                    int mm = m + ((e >= 2) ? 8 : 0);
                    int n = c0 + (e & 1);
                    if (n >= N) continue;
                    float v = acc[mt][nt][e];
                    Cf[(size_t)mm * ldc + n] = v;
                    if (n < DTRANK)
                        e_dtr[(size_t)mm * DTRANK + n] = __float2half_rn(v);
                }
            }
        }
    } else {  // OP 4
#pragma unroll
        for (int mt = 0; mt < 2; mt++) {
            int m = rowBase + wm * 32 + mt * 16 + (lane >> 2);
#pragma unroll
            for (int nt = 0; nt < NFR; nt++) {
                int c0 = colBase + wn * WCOLS + nt * 8 + (lane & 3) * 2;
#pragma unroll
                for (int half8 = 0; half8 < 2; half8++) {
                    int mm = m + half8 * 8;
                    float v0 = acc[mt][nt][half8 * 2 + 0];
                    float v1 = acc[mt][nt][half8 * 2 + 1];
                    *(__half2*)(Ch + (size_t)mm * ldc + c0) = __floats2half2_rn(v0, v1);
                }
            }
        }
    }
}

// ==================== fused weight-convert + LayerNorm ====================
struct Cvt4 {
    const float* in0; const float* in1; const float* in2; const float* in3;
    __half* out0; __half* out1; __half* out2; __half* out3;
    int c0, c1, c2, c3;
};
#define LN_BLOCKS (TOKS / 4)
__global__ __launch_bounds__(256) void cvt_ln_kernel(Cvt4 c,
                                                     const float* __restrict__ x,
                                                     const float* __restrict__ w,
                                                     const float* __restrict__ bvec) {
    if (blockIdx.x >= LN_BLOCKS) {
        int i = (blockIdx.x - LN_BLOCKS) * 256 + threadIdx.x;
        if (i >= c.c3) return;
        const float* in; __half* out; int j;
        if (i < c.c0)      { in = c.in0; out = c.out0; j = i; }
        else if (i < c.c1) { in = c.in1; out = c.out1; j = i - c.c0; }
        else if (i < c.c2) { in = c.in2; out = c.out2; j = i - c.c1; }
        else               { in = c.in3; out = c.out3; j = i - c.c2; }
        float2 v = *(const float2*)(in + (size_t)j * 2);
        *(__half2*)(out + (size_t)j * 2) = __floats2half2_rn(v.x, v.y);
        return;
    }
    int blk = blockIdx.x;
    int b  = blk >> 8;
    int t0 = (blk & 255) * 4;
    int c0 = threadIdx.x * 4;

    float va[4][4];
    float s[4] = {0, 0, 0, 0}, s2[4] = {0, 0, 0, 0};
#pragma unroll
    for (int ci = 0; ci < 4; ci++) {
        float4 v = *(const float4*)(x + (size_t)b * CC * TT + (size_t)(c0 + ci) * TT + t0);
        va[ci][0] = v.x; va[ci][1] = v.y; va[ci][2] = v.z; va[ci][3] = v.w;
#pragma unroll
        for (int t = 0; t < 4; t++) {
            s[t] += va[ci][t];
            s2[t] = fmaf(va[ci][t], va[ci][t], s2[t]);
        }
    }
#pragma unroll
    for (int o = 16; o; o >>= 1)
#pragma unroll
        for (int t = 0; t < 4; t++) {
            s[t]  += __shfl_xor_sync(0xffffffffu, s[t],  o);
            s2[t] += __shfl_xor_sync(0xffffffffu, s2[t], o);
        }
    __shared__ float sh[8][8];
    int wp = threadIdx.x >> 5, ln = threadIdx.x & 31;
    if (ln == 0) {
#pragma unroll
        for (int t = 0; t < 4; t++) { sh[t][wp] = s[t]; sh[4 + t][wp] = s2[t]; }
    }
    __syncthreads();
    float mu[4], rs[4];
#pragma unroll
    for (int t = 0; t < 4; t++) {
        float S = 0.f, S2 = 0.f;
#pragma unroll
        for (int i = 0; i < 8; i++) { S += sh[t][i]; S2 += sh[4 + t][i]; }
        mu[t] = S * (1.f / 1024.f);
        float var = S2 * (1.f / 1024.f) - mu[t] * mu[t];
        rs[t] = rsqrtf(var + 1e-5f);
    }
    float wv[4], bv[4];
#pragma unroll
    for (int ci = 0; ci < 4; ci++) { wv[ci] = w[c0 + ci]; bv[ci] = bvec[c0 + ci]; }
#pragma unroll
    for (int t = 0; t < 4; t++) {
        int tok = b * TT + t0 + t;
        float o0 = (va[0][t] - mu[t]) * rs[t] * wv[0] + bv[0];
        float o1 = (va[1][t] - mu[t]) * rs[t] * wv[1] + bv[1];
        float o2 = (va[2][t] - mu[t]) * rs[t] * wv[2] + bv[2];
        float o3 = (va[3][t] - mu[t]) * rs[t] * wv[3] + bv[3];
        __half2* op = (__half2*)(e_xn + (size_t)tok * CC + c0);
        op[0] = __floats2half2_rn(o0, o1);
        op[1] = __floats2half2_rn(o2, o3);
    }
}

// conv+SiLU
__global__ __launch_bounds__(256) void conv_silu_kernel(const float* __restrict__ conv_w,
                                                        const float* __restrict__ conv_b) {
    int i = blockIdx.x * 256 + threadIdx.x;
    int d = i & (DIN - 1);
    int tg = i >> 11;
    int b = tg >> 8;
    int t0 = (tg & 255) * 4;

    float w0 = conv_w[d * DCONV + 0];
    float w1 = conv_w[d * DCONV + 1];
    float w2 = conv_w[d * DCONV + 2];
    float w3 = conv_w[d * DCONV + 3];
    float bias = conv_b[d];

    const __half* xin = e_xz + (size_t)(b * TT) * (2 * DIN) + d;
    float xv[7];
#pragma unroll
    for (int j = 0; j < 7; j++) {
        int t = t0 - 3 + j;
        xv[j] = (t >= 0) ? __half2float(xin[(size_t)t * (2 * DIN)]) : 0.f;
    }
#pragma unroll
    for (int k = 0; k < 4; k++) {
        float v = bias;
        v = fmaf(w0, xv[k],     v);
        v = fmaf(w1, xv[k + 1], v);
        v = fmaf(w2, xv[k + 2], v);
        v = fmaf(w3, xv[k + 3], v);
        float sig = 1.f / (1.f + __expf(-v));
        e_xc[(size_t)(b * TT + t0 + k) * DIN + d] = __float2half_rn(v * sig);
    }
}

// ==================== scan v5: 16 ch/block, 128 thr, 2 blocks/SM, fused dt_proj ====================
// dynamic smem (bytes):
#define S_DTR  0               // [2][64*64] half  = 16384
#define S_XC   16384           // [2][64*16] half  = 4096
#define S_Z    20480           // [2][64*16] half  = 4096
#define S_BC   24576           // [2][64*32] float = 16384
#define S_W3   40960           // [16*64] half     = 2048
#define S_DT   43008           // [64*16] float    = 4096
#define S_Y    47104           // [64*16] float    = 4096
#define SCAN_SMEM 51200

__global__ __launch_bounds__(128, 2) void scan_kernel(const float* __restrict__ A_log,
                                                      const float* __restrict__ Dvec,
                                                      const float* __restrict__ dt_b) {
    extern __shared__ char sm[];
    uint32_t base = smem_u32(sm);
    __half* sXC = (__half*)(sm + S_XC);
    __half* sZ  = (__half*)(sm + S_Z);
    float*  sBC = (float*)(sm + S_BC);
    float*  sDT = (float*)(sm + S_DT);
    float*  sY  = (float*)(sm + S_Y);

    int tid  = threadIdx.x;
    int lane = tid & 31, warp = tid >> 5;     // 4 warps
    int chBase = blockIdx.x * 16;             // 256 blocks
    int b  = chBase >> 11;
    int d0 = chBase & (DIN - 1);
    int cloc = lane >> 3;
    int s    = lane & 7;                      // states s, s+8
    int dloc = warp * 4 + cloc;               // 0..15
    int d = d0 + dloc;

    float A1 = -__expf(A_log[d * DSTATE + s]);
    float A2 = -__expf(A_log[d * DSTATE + s + 8]);
    float Dd = Dvec[d];

    const __half* dtrG = e_dtr + (size_t)(b * TT) * DTRANK;
    const __half* xcH  = e_xc + (size_t)(b * TT) * DIN + d0;
    const __half* zH   = e_xz + (size_t)(b * TT) * (2 * DIN) + DIN + d0;
    const float*  bcG  = g_xdbl + (size_t)(b * TT) * XDBL + DTRANK;

    // W3 slice [16 rows x 64], swizzled; 128 chunks, 1 per thread
    {
        int row = tid >> 3, c = tid & 7;
        cp16(base + S_W3 + row * 128 + ((c ^ (row & 7)) << 4),
             e_w3 + (size_t)(d0 + row) * DTRANK + c * 8, true);
    }

    auto load_win = [&](int w, int buf) {
        int t0 = w * SW;
#pragma unroll
        for (int k = 0; k < 10; k++) {            // 1280 chunks / 128 threads
            int i = tid + k * 128;
            uint32_t dst; const void* src;
            if (i < 512) {                        // dtr: 64t x 8 units, swizzled
                int t = i >> 3, c = i & 7;
                dst = base + S_DTR + buf * 8192 + t * 128 + ((c ^ (t & 7)) << 4);
                src = dtrG + (size_t)(t0 + t) * DTRANK + c * 8;
            } else if (i < 640) {                 // xc: 64t x 2 units
                int r = i - 512;
                int t = r >> 1, seg = r & 1;
                dst = base + S_XC + buf * 2048 + t * 32 + seg * 16;
                src = xcH + (size_t)(t0 + t) * DIN + seg * 8;
            } else if (i < 768) {                 // z
                int r = i - 640;
                int t = r >> 1, seg = r & 1;
                dst = base + S_Z + buf * 2048 + t * 32 + seg * 16;
                src = zH + (size_t)(t0 + t) * (2 * DIN) + seg * 8;
            } else {                              // bc: 64t x 8 units fp32
                int r = i - 768;
                int t = r >> 3, seg = r & 7;
                dst = base + S_BC + buf * 8192 + t * 128 + seg * 16;
                src = bcG + (size_t)(t0 + t) * XDBL + seg * 4;
            }
            cp16(dst, src, true);
        }
        asm volatile("cp.async.commit_group;\n");
    };

    constexpr int NW = TT / SW;
    load_win(0, 0);
    int buf = 0;
    float h1 = 0.f, h2 = 0.f;

    for (int w = 0; w < NW; w++) {
        if (w + 1 < NW) {
            load_win(w + 1, buf ^ 1);
            asm volatile("cp.async.wait_group 1;\n");
        } else {
            asm volatile("cp.async.wait_group 0;\n");
        }
        __syncthreads();

        // ---- prepass: dt[64t x 16d] = softplus(dtr @ W3^T + b) ----
        {
            int mt = warp;                         // 16 t-rows per warp
            float acc[2][4] = {{0, 0, 0, 0}, {0, 0, 0, 0}};
#pragma unroll
            for (int ks = 0; ks < 4; ks++) {
                uint32_t a0, a1, a2, a3;
                int arow = mt * 16 + (lane & 15);
                int unit = ks * 2 + (lane >> 4);
                ldsm4(a0, a1, a2, a3,
                      base + S_DTR + buf * 8192 + arow * 128 + ((unit ^ (arow & 7)) << 4));
                uint32_t r0, r1, r2, r3;
                int brow = lane & 15;
                ldsm4(r0, r1, r2, r3,
                      base + S_W3 + brow * 128 + ((unit ^ (brow & 7)) << 4));
                uint32_t af[4] = {a0, a1, a2, a3};
                uint32_t bf0[2] = {r0, r2};
                uint32_t bf1[2] = {r1, r3};
                mma16816(acc[0], af, bf0);
                mma16816(acc[1], af, bf1);
            }
#pragma unroll
            for (int f = 0; f < 2; f++)
#pragma unroll
                for (int e = 0; e < 4; e++) {
                    int tl = mt * 16 + (lane >> 2) + ((e >= 2) ? 8 : 0);
                    int dl = f * 8 + (lane & 3) * 2 + (e & 1);
                    float v = acc[f][e] + __ldg(dt_b + d0 + dl);
                    v = (v > 20.f) ? v : log1pf(__expf(v));
                    sDT[tl * 16 + dl] = v;
                }
        }
        __syncthreads();

        // ---- serial scan ----
        const __half* fXC = sXC + buf * 1024;
        const float*  fBC = sBC + buf * 2048;
#pragma unroll 4
        for (int t = 0; t < SW; t++) {
            float dtv = sDT[t * 16 + dloc];
            float xv  = __half2float(fXC[t * 16 + dloc]);
            float B1  = fBC[t * 32 + s];
            float B2  = fBC[t * 32 + 8 + s];
            float C1  = fBC[t * 32 + 16 + s];
            float C2  = fBC[t * 32 + 24 + s];
            float dA1 = __expf(dtv * A1);
            float dA2 = __expf(dtv * A2);
            float dbx = dtv * xv;
            h1 = fmaf(dA1, h1, dbx * B1);
            h2 = fmaf(dA2, h2, dbx * B2);
            float p = fmaf(h2, C2, h1 * C1);
            p += __shfl_xor_sync(0xffffffffu, p, 4);
            p += __shfl_xor_sync(0xffffffffu, p, 2);
            p += __shfl_xor_sync(0xffffffffu, p, 1);
            if (s == 0) sY[t * 16 + dloc] = fmaf(Dd, xv, p);
        }
        __syncthreads();

        // ---- gated writeback: 64t x 16d = 1024 elems ----
        const __half* fZ = sZ + buf * 1024;
        int t0 = w * SW;
#pragma unroll
        for (int k = 0; k < 8; k++) {
            int idx = tid + k * 128;
            int t = idx >> 4, dd = idx & 15;
            float yv = sY[t * 16 + dd];
            float zv = __half2float(fZ[t * 16 + dd]);
            float sig = 1.f / (1.f + __expf(-zv));
            yv *= zv * sig;
            e_y[(size_t)(b * TT + t0 + t) * DIN + d0 + dd] = __float2half_rn(yv);
        }
        __syncthreads();
        buf ^= 1;
    }
}

// ==================== launch ====================
extern "C" void kernel_launch(void* const* d_in, const int* in_sizes, int n_in,
                              void* d_out, int out_size) {
    const float* x          = (const float*)d_in[0];
    const float* norm_w     = (const float*)d_in[1];
    const float* norm_b     = (const float*)d_in[2];
    const float* in_proj_w  = (const float*)d_in[3];
    const float* conv_w     = (const float*)d_in[4];
    const float* conv_b     = (const float*)d_in[5];
    const float* x_proj_w   = (const float*)d_in[6];
    const float* dt_proj_w  = (const float*)d_in[7];
    const float* dt_proj_b  = (const float*)d_in[8];
    const float* A_log      = (const float*)d_in[9];
    const float* Dvec       = (const float*)d_in[10];
    const float* out_proj_w = (const float*)d_in[11];
    float* out = (float*)d_out;

    float *xdbl;
    __half *exn, *ew1, *exz, *exc, *ew2, *ew3, *ey, *ew4;
    cudaGetSymbolAddress((void**)&xdbl, g_xdbl);
    cudaGetSymbolAddress((void**)&exn,  e_xn);
    cudaGetSymbolAddress((void**)&ew1,  e_w1);
    cudaGetSymbolAddress((void**)&exz,  e_xz);
    cudaGetSymbolAddress((void**)&exc,  e_xc);
    cudaGetSymbolAddress((void**)&ew2,  e_w2);
    cudaGetSymbolAddress((void**)&ew3,  e_w3);
    cudaGetSymbolAddress((void**)&ey,   e_y);
    cudaGetSymbolAddress((void**)&ew4,  e_w4);

    const int smem128 = 3 * (128 * 128 + 128 * 128);   // 98304
    cudaFuncSetAttribute(gemm_mma<4, 128>, cudaFuncAttributeMaxDynamicSharedMemorySize, smem128);
    cudaFuncSetAttribute(gemm_mma<5, 128>, cudaFuncAttributeMaxDynamicSharedMemorySize, smem128);
    cudaFuncSetAttribute(gemm_mma<2, 128>, cudaFuncAttributeMaxDynamicSharedMemorySize, smem128);
    cudaFuncSetAttribute(scan_kernel, cudaFuncAttributeMaxDynamicSharedMemorySize, SCAN_SMEM);

    // 1. fused weight converts + LayerNorm
    Cvt4 cv;
    cv.in0 = in_proj_w;  cv.out0 = ew1;
    cv.in1 = out_proj_w; cv.out1 = ew4;
    cv.in2 = x_proj_w;   cv.out2 = ew2;
    cv.in3 = dt_proj_w;  cv.out3 = ew3;
    int n0 = 2 * DIN * CC / 2, n1 = CC * DIN / 2, n2 = XDBL * DIN / 2, n3 = DIN * DTRANK / 2;
    cv.c0 = n0; cv.c1 = n0 + n1; cv.c2 = n0 + n1 + n2; cv.c3 = n0 + n1 + n2 + n3;
    int cvtBlocks = (cv.c3 + 255) / 256;
    cvt_ln_kernel<<<LN_BLOCKS + cvtBlocks, 256>>>(cv, x, norm_w, norm_b);
    // 2. in_proj -> e_xz fp16
    gemm_mma<4, 128><<<dim3((2 * DIN) / 128, TOKS / 128), 256, smem128>>>(
        exn, CC, ew1, CC, exz, 2 * DIN, TOKS, 2 * DIN, CC, nullptr);
    // 3. conv + SiLU
    conv_silu_kernel<<<(TOKS / 4) * DIN / 256, 256>>>(conv_w, conv_b);
    // 4. x_proj non-split, fused reduce epilogue (PROFILED LAUNCH)
    gemm_mma<5, 128><<<dim3(1, TOKS / 128), 256, smem128>>>(
        exc, DIN, ew2, DIN, xdbl, XDBL, TOKS, XDBL, DIN, nullptr);
    // 5. scan v5 (fused dt_proj + scan + gate, 2 blocks/SM)
    scan_kernel<<<(BB * DIN) / 16, 128, SCAN_SMEM>>>(A_log, Dvec, dt_proj_b);
    // 6. out_proj + residual, transposed store
    gemm_mma<2, 128><<<dim3(CC / 128, TOKS / 128), 256, smem128>>>(
        ey, DIN, ew4, DIN, out, 0, TOKS, CC, DIN, x);
}

// round 16
// speedup vs baseline: 1.0827x; 1.0827x over previous
#include <cuda_runtime.h>
#include <cuda_fp16.h>
#include <math.h>
#include <stdint.h>

// ---------------- problem constants ----------------
#define BB      2
#define CC      1024
#define TT      1024
#define TOKS    (BB * TT)          // 2048
#define DIN     2048
#define DSTATE  16
#define DTRANK  64
#define XDBL    96
#define DCONV   4
#define SPLITK  8
#define SW      64                 // scan window (t-steps)

// ---------------- fp32 scratch ----------------
__device__ float g_xdbl[TOKS * XDBL];
__device__ float g_part[SPLITK * TOKS * XDBL];

// ---------------- fp16 scratch ----------------
__device__ __half e_xn [TOKS * CC];
__device__ __half e_w1 [2 * DIN * CC];
__device__ __half e_xz [TOKS * 2 * DIN];
__device__ __half e_xc [TOKS * DIN];
__device__ __half e_w2 [XDBL * DIN];
__device__ __half e_dtr[TOKS * DTRANK];
__device__ __half e_w3 [DIN * DTRANK];
__device__ __half e_y  [TOKS * DIN];
__device__ __half e_w4 [CC * DIN];

// ==================== PTX helpers ====================
__device__ __forceinline__ uint32_t smem_u32(const void* p) {
    uint32_t a;
    asm("{ .reg .u64 t; cvta.to.shared.u64 t, %1; cvt.u32.u64 %0, t; }" : "=r"(a) : "l"(p));
    return a;
}
__device__ __forceinline__ void cp16(uint32_t dst, const void* src, bool pred) {
    int sz = pred ? 16 : 0;
    asm volatile("cp.async.cg.shared.global [%0], [%1], 16, %2;\n" :: "r"(dst), "l"(src), "r"(sz));
}
__device__ __forceinline__ void ldsm4(uint32_t& r0, uint32_t& r1, uint32_t& r2, uint32_t& r3,
                                      uint32_t addr) {
    asm volatile("ldmatrix.sync.aligned.m8n8.x4.shared.b16 {%0,%1,%2,%3}, [%4];"
                 : "=r"(r0), "=r"(r1), "=r"(r2), "=r"(r3) : "r"(addr));
}
__device__ __forceinline__ void mma16816(float* c, const uint32_t* a, const uint32_t* b) {
    asm volatile("mma.sync.aligned.m16n8k16.row.col.f32.f16.f16.f32 "
                 "{%0,%1,%2,%3}, {%4,%5,%6,%7}, {%8,%9}, {%0,%1,%2,%3};"
                 : "+f"(c[0]), "+f"(c[1]), "+f"(c[2]), "+f"(c[3])
                 : "r"(a[0]), "r"(a[1]), "r"(a[2]), "r"(a[3]), "r"(b[0]), "r"(b[1]));
}

// ==================== mma.sync fp16 GEMM ====================
// OP 2: transpose+residual fp32 | OP 3: split-K fp32 partials | OP 4: plain fp16 store
template <int OP, int NT>
__global__ __launch_bounds__(256, 2)
void gemm_mma(const __half* __restrict__ A, int lda,
              const __half* __restrict__ W, int ldw,
              void* __restrict__ Cout, int ldc,
              int M, int N, int Kext,
              const float* __restrict__ resid) {
    constexpr int SA     = 128 * 128;
    constexpr int SB     = NT * 128;
    constexpr int STAGE  = SA + SB;
    constexpr int WCOLS  = NT / 2;
    constexpr int NFR    = WCOLS / 8;
    constexpr int BLD    = WCOLS / 16;
    constexpr int BCHUNK = NT * 8 / 256;

    extern __shared__ float4 dyn4[];
    uint32_t base = smem_u32(dyn4);

    int tid = threadIdx.x, lane = tid & 31, warp = tid >> 5;
    int wm = warp & 3, wn = warp >> 2;
    int rowBase = blockIdx.y * 128, colBase = blockIdx.x * NT;

    float* Cf = (float*)Cout;
    __half* Ch = (__half*)Cout;

    int kStart = 0;
    if (OP == 3) {
        int ch = Kext / SPLITK;
        kStart = blockIdx.z * ch;
        Kext = ch;
        Cf += (size_t)blockIdx.z * M * ldc;
    }
    int nTiles = Kext / 64;

    float acc[2][NFR][4];
#pragma unroll
    for (int i = 0; i < 2; i++)
#pragma unroll
        for (int j = 0; j < NFR; j++)
#pragma unroll
            for (int e = 0; e < 4; e++) acc[i][j][e] = 0.f;

    auto load_tile = [&](int s, int kt) {
        uint32_t aB = base + s * STAGE, bB = aB + SA;
        int k0 = kStart + kt * 64;
#pragma unroll
        for (int i = 0; i < 4; i++) {
            int idx = tid + i * 256;
            int row = idx >> 3, c = idx & 7;
            cp16(aB + row * 128 + ((c ^ (row & 7)) << 4),
                 A + (size_t)(rowBase + row) * lda + k0 + c * 8, true);
        }
#pragma unroll
        for (int i = 0; i < BCHUNK; i++) {
            int idx = tid + i * 256;
            int row = idx >> 3, c = idx & 7;
            bool ok = (colBase + row) < N;
            cp16(bB + row * 128 + ((c ^ (row & 7)) << 4),
                 W + (ok ? (size_t)(colBase + row) * ldw : 0) + k0 + c * 8, ok);
        }
        asm volatile("cp.async.commit_group;\n");
    };

    load_tile(0, 0);
    if (nTiles > 1) load_tile(1, 1);

    for (int t = 0; t < nTiles; t++) {
        if (t + 1 >= nTiles) asm volatile("cp.async.wait_group 0;\n");
        else                 asm volatile("cp.async.wait_group 1;\n");
        __syncthreads();

        int s = t % 3;
        uint32_t aB = base + s * STAGE, bB = aB + SA;
#pragma unroll
        for (int ks = 0; ks < 4; ks++) {
            uint32_t afr[2][4];
#pragma unroll
            for (int mt = 0; mt < 2; mt++) {
                int row = wm * 32 + mt * 16 + (lane & 15);
                int unit = ks * 2 + (lane >> 4);
                ldsm4(afr[mt][0], afr[mt][1], afr[mt][2], afr[mt][3],
                      aB + row * 128 + ((unit ^ (row & 7)) << 4));
            }
            uint32_t bfr[NFR][2];
#pragma unroll
            for (int p = 0; p < BLD; p++) {
                int row = wn * WCOLS + p * 16 + (lane & 15);
                int unit = ks * 2 + (lane >> 4);
                uint32_t r0, r1, r2, r3;
                ldsm4(r0, r1, r2, r3, bB + row * 128 + ((unit ^ (row & 7)) << 4));
                bfr[2 * p][0] = r0; bfr[2 * p + 1][0] = r1;
                bfr[2 * p][1] = r2; bfr[2 * p + 1][1] = r3;
            }
#pragma unroll
            for (int mt = 0; mt < 2; mt++)
#pragma unroll
                for (int nt = 0; nt < NFR; nt++)
                    mma16816(acc[mt][nt], afr[mt], bfr[nt]);
        }
        if (t + 2 < nTiles) load_tile((t + 2) % 3, t + 2);
    }

    if (OP == 2) {
        __syncthreads();
        float* st = (float*)dyn4;
        const int PITCH = 132;
#pragma unroll
        for (int mt = 0; mt < 2; mt++)
#pragma unroll
            for (int nt = 0; nt < NFR; nt++)
#pragma unroll
                for (int e = 0; e < 4; e++) {
                    int ml = wm * 32 + mt * 16 + (lane >> 2) + ((e >= 2) ? 8 : 0);
                    int nl = wn * WCOLS + nt * 8 + (lane & 3) * 2 + (e & 1);
                    st[nl * PITCH + ml] = acc[mt][nt][e];
                }
        __syncthreads();
        int b = rowBase >> 10, t0 = rowBase & 1023;
        for (int r = warp; r < 128; r += 8) {
            float4 v = *(float4*)&st[r * PITCH + lane * 4];
            size_t oi = (size_t)b * CC * TT + (size_t)(colBase + r) * TT + t0 + lane * 4;
            float4 rv = *(const float4*)(resid + oi);
            v.x += rv.x; v.y += rv.y; v.z += rv.z; v.w += rv.w;
            *(float4*)(Cf + oi) = v;
        }
    } else if (OP == 3) {
#pragma unroll
        for (int mt = 0; mt < 2; mt++) {
            int m = rowBase + wm * 32 + mt * 16 + (lane >> 2);
#pragma unroll
            for (int nt = 0; nt < NFR; nt++) {
                int c0 = colBase + wn * WCOLS + nt * 8 + (lane & 3) * 2;
#pragma unroll
                for (int e = 0; e < 4; e++) {
                    int mm = m + ((e >= 2) ? 8 : 0);
                    int n = c0 + (e & 1);
                    if (n >= N) continue;
                    Cf[(size_t)mm * ldc + n] = acc[mt][nt][e];
                }
            }
        }
    } else {  // OP 4
#pragma unroll
        for (int mt = 0; mt < 2; mt++) {
            int m = rowBase + wm * 32 + mt * 16 + (lane >> 2);
#pragma unroll
            for (int nt = 0; nt < NFR; nt++) {
                int c0 = colBase + wn * WCOLS + nt * 8 + (lane & 3) * 2;
#pragma unroll
                for (int half8 = 0; half8 < 2; half8++) {
                    int mm = m + half8 * 8;
                    float v0 = acc[mt][nt][half8 * 2 + 0];
                    float v1 = acc[mt][nt][half8 * 2 + 1];
                    *(__half2*)(Ch + (size_t)mm * ldc + c0) = __floats2half2_rn(v0, v1);
                }
            }
        }
    }
}

// ==================== fused weight-convert + LayerNorm ====================
struct Cvt4 {
    const float* in0; const float* in1; const float* in2; const float* in3;
    __half* out0; __half* out1; __half* out2; __half* out3;
    int c0, c1, c2, c3;
};
#define LN_BLOCKS (TOKS / 4)
__global__ __launch_bounds__(256) void cvt_ln_kernel(Cvt4 c,
                                                     const float* __restrict__ x,
                                                     const float* __restrict__ w,
                                                     const float* __restrict__ bvec) {
    if (blockIdx.x >= LN_BLOCKS) {
        int i = (blockIdx.x - LN_BLOCKS) * 256 + threadIdx.x;
        if (i >= c.c3) return;
        const float* in; __half* out; int j;
        if (i < c.c0)      { in = c.in0; out = c.out0; j = i; }
        else if (i < c.c1) { in = c.in1; out = c.out1; j = i - c.c0; }
        else if (i < c.c2) { in = c.in2; out = c.out2; j = i - c.c1; }
        else               { in = c.in3; out = c.out3; j = i - c.c2; }
        float2 v = *(const float2*)(in + (size_t)j * 2);
        *(__half2*)(out + (size_t)j * 2) = __floats2half2_rn(v.x, v.y);
        return;
    }
    int blk = blockIdx.x;
    int b  = blk >> 8;
    int t0 = (blk & 255) * 4;
    int c0 = threadIdx.x * 4;

    float va[4][4];
    float s[4] = {0, 0, 0, 0}, s2[4] = {0, 0, 0, 0};
#pragma unroll
    for (int ci = 0; ci < 4; ci++) {
        float4 v = *(const float4*)(x + (size_t)b * CC * TT + (size_t)(c0 + ci) * TT + t0);
        va[ci][0] = v.x; va[ci][1] = v.y; va[ci][2] = v.z; va[ci][3] = v.w;
#pragma unroll
        for (int t = 0; t < 4; t++) {
            s[t] += va[ci][t];
            s2[t] = fmaf(va[ci][t], va[ci][t], s2[t]);
        }
    }
#pragma unroll
    for (int o = 16; o; o >>= 1)
#pragma unroll
        for (int t = 0; t < 4; t++) {
            s[t]  += __shfl_xor_sync(0xffffffffu, s[t],  o);
            s2[t] += __shfl_xor_sync(0xffffffffu, s2[t], o);
        }
    __shared__ float sh[8][8];
    int wp = threadIdx.x >> 5, ln = threadIdx.x & 31;
    if (ln == 0) {
#pragma unroll
        for (int t = 0; t < 4; t++) { sh[t][wp] = s[t]; sh[4 + t][wp] = s2[t]; }
    }
    __syncthreads();
    float mu[4], rs[4];
#pragma unroll
    for (int t = 0; t < 4; t++) {
        float S = 0.f, S2 = 0.f;
#pragma unroll
        for (int i = 0; i < 8; i++) { S += sh[t][i]; S2 += sh[4 + t][i]; }
        mu[t] = S * (1.f / 1024.f);
        float var = S2 * (1.f / 1024.f) - mu[t] * mu[t];
        rs[t] = rsqrtf(var + 1e-5f);
    }
    float wv[4], bv[4];
#pragma unroll
    for (int ci = 0; ci < 4; ci++) { wv[ci] = w[c0 + ci]; bv[ci] = bvec[c0 + ci]; }
#pragma unroll
    for (int t = 0; t < 4; t++) {
        int tok = b * TT + t0 + t;
        float o0 = (va[0][t] - mu[t]) * rs[t] * wv[0] + bv[0];
        float o1 = (va[1][t] - mu[t]) * rs[t] * wv[1] + bv[1];
        float o2 = (va[2][t] - mu[t]) * rs[t] * wv[2] + bv[2];
        float o3 = (va[3][t] - mu[t]) * rs[t] * wv[3] + bv[3];
        __half2* op = (__half2*)(e_xn + (size_t)tok * CC + c0);
        op[0] = __floats2half2_rn(o0, o1);
        op[1] = __floats2half2_rn(o2, o3);
    }
}

// split-K reduce -> g_xdbl fp32 + e_dtr fp16
__global__ __launch_bounds__(256) void reduce_part_kernel() {
    int i = blockIdx.x * 256 + threadIdx.x;
    if (i >= TOKS * XDBL) return;
    float s = 0.f;
#pragma unroll
    for (int z = 0; z < SPLITK; z++) s += g_part[(size_t)z * TOKS * XDBL + i];
    g_xdbl[i] = s;
    int tok = i / XDBL, k = i - tok * XDBL;
    if (k < DTRANK) e_dtr[(size_t)tok * DTRANK + k] = __float2half_rn(s);
}

// conv+SiLU
__global__ __launch_bounds__(256) void conv_silu_kernel(const float* __restrict__ conv_w,
                                                        const float* __restrict__ conv_b) {
    int i = blockIdx.x * 256 + threadIdx.x;
    int d = i & (DIN - 1);
    int tg = i >> 11;
    int b = tg >> 8;
    int t0 = (tg & 255) * 4;

    float w0 = conv_w[d * DCONV + 0];
    float w1 = conv_w[d * DCONV + 1];
    float w2 = conv_w[d * DCONV + 2];
    float w3 = conv_w[d * DCONV + 3];
    float bias = conv_b[d];

    const __half* xin = e_xz + (size_t)(b * TT) * (2 * DIN) + d;
    float xv[7];
#pragma unroll
    for (int j = 0; j < 7; j++) {
        int t = t0 - 3 + j;
        xv[j] = (t >= 0) ? __half2float(xin[(size_t)t * (2 * DIN)]) : 0.f;
    }
#pragma unroll
    for (int k = 0; k < 4; k++) {
        float v = bias;
        v = fmaf(w0, xv[k],     v);
        v = fmaf(w1, xv[k + 1], v);
        v = fmaf(w2, xv[k + 2], v);
        v = fmaf(w3, xv[k + 3], v);
        float sig = 1.f / (1.f + __expf(-v));
        e_xc[(size_t)(b * TT + t0 + k) * DIN + d] = __float2half_rn(v * sig);
    }
}

// ==================== scan v5: 16 ch/block, 128 thr, 2 blocks/SM, fused dt_proj ====================
#define S_DTR  0               // [2][64*64] half  = 16384
#define S_XC   16384           // [2][64*16] half  = 4096
#define S_Z    20480           // [2][64*16] half  = 4096
#define S_BC   24576           // [2][64*32] float = 16384
#define S_W3   40960           // [16*64] half     = 2048
#define S_DT   43008           // [64*16] float    = 4096
#define S_Y    47104           // [64*16] float    = 4096
#define SCAN_SMEM 51200

__global__ __launch_bounds__(128, 2) void scan_kernel(const float* __restrict__ A_log,
                                                      const float* __restrict__ Dvec,
                                                      const float* __restrict__ dt_b) {
    extern __shared__ char sm[];
    uint32_t base = smem_u32(sm);
    __half* sXC = (__half*)(sm + S_XC);
    __half* sZ  = (__half*)(sm + S_Z);
    float*  sBC = (float*)(sm + S_BC);
    float*  sDT = (float*)(sm + S_DT);
    float*  sY  = (float*)(sm + S_Y);

    int tid  = threadIdx.x;
    int lane = tid & 31, warp = tid >> 5;
    int chBase = blockIdx.x * 16;
    int b  = chBase >> 11;
    int d0 = chBase & (DIN - 1);
    int cloc = lane >> 3;
    int s    = lane & 7;
    int dloc = warp * 4 + cloc;
    int d = d0 + dloc;

    float A1 = -__expf(A_log[d * DSTATE + s]);
    float A2 = -__expf(A_log[d * DSTATE + s + 8]);
    float Dd = Dvec[d];

    const __half* dtrG = e_dtr + (size_t)(b * TT) * DTRANK;
    const __half* xcH  = e_xc + (size_t)(b * TT) * DIN + d0;
    const __half* zH   = e_xz + (size_t)(b * TT) * (2 * DIN) + DIN + d0;
    const float*  bcG  = g_xdbl + (size_t)(b * TT) * XDBL + DTRANK;

    {
        int row = tid >> 3, c = tid & 7;
        cp16(base + S_W3 + row * 128 + ((c ^ (row & 7)) << 4),
             e_w3 + (size_t)(d0 + row) * DTRANK + c * 8, true);
    }

    auto load_win = [&](int w, int buf) {
        int t0 = w * SW;
#pragma unroll
        for (int k = 0; k < 10; k++) {
            int i = tid + k * 128;
            uint32_t dst; const void* src;
            if (i < 512) {
                int t = i >> 3, c = i & 7;
                dst = base + S_DTR + buf * 8192 + t * 128 + ((c ^ (t & 7)) << 4);
                src = dtrG + (size_t)(t0 + t) * DTRANK + c * 8;
            } else if (i < 640) {
                int r = i - 512;
                int t = r >> 1, seg = r & 1;
                dst = base + S_XC + buf * 2048 + t * 32 + seg * 16;
                src = xcH + (size_t)(t0 + t) * DIN + seg * 8;
            } else if (i < 768) {
                int r = i - 640;
                int t = r >> 1, seg = r & 1;
                dst = base + S_Z + buf * 2048 + t * 32 + seg * 16;
                src = zH + (size_t)(t0 + t) * (2 * DIN) + seg * 8;
            } else {
                int r = i - 768;
                int t = r >> 3, seg = r & 7;
                dst = base + S_BC + buf * 8192 + t * 128 + seg * 16;
                src = bcG + (size_t)(t0 + t) * XDBL + seg * 4;
            }
            cp16(dst, src, true);
        }
        asm volatile("cp.async.commit_group;\n");
    };

    constexpr int NW = TT / SW;
    load_win(0, 0);
    int buf = 0;
    float h1 = 0.f, h2 = 0.f;

    for (int w = 0; w < NW; w++) {
        if (w + 1 < NW) {
            load_win(w + 1, buf ^ 1);
            asm volatile("cp.async.wait_group 1;\n");
        } else {
            asm volatile("cp.async.wait_group 0;\n");
        }
        __syncthreads();

        // ---- prepass: dt[64t x 16d] = softplus(dtr @ W3^T + b) ----
        {
            int mt = warp;
            float acc[2][4] = {{0, 0, 0, 0}, {0, 0, 0, 0}};
#pragma unroll
            for (int ks = 0; ks < 4; ks++) {
                uint32_t a0, a1, a2, a3;
                int arow = mt * 16 + (lane & 15);
                int unit = ks * 2 + (lane >> 4);
                ldsm4(a0, a1, a2, a3,
                      base + S_DTR + buf * 8192 + arow * 128 + ((unit ^ (arow & 7)) << 4));
                uint32_t r0, r1, r2, r3;
                int brow = lane & 15;
                ldsm4(r0, r1, r2, r3,
                      base + S_W3 + brow * 128 + ((unit ^ (brow & 7)) << 4));
                uint32_t af[4] = {a0, a1, a2, a3};
                uint32_t bf0[2] = {r0, r2};
                uint32_t bf1[2] = {r1, r3};
                mma16816(acc[0], af, bf0);
                mma16816(acc[1], af, bf1);
            }
#pragma unroll
            for (int f = 0; f < 2; f++)
#pragma unroll
                for (int e = 0; e < 4; e++) {
                    int tl = mt * 16 + (lane >> 2) + ((e >= 2) ? 8 : 0);
                    int dl = f * 8 + (lane & 3) * 2 + (e & 1);
                    float v = acc[f][e] + __ldg(dt_b + d0 + dl);
                    v = (v > 20.f) ? v : log1pf(__expf(v));
                    sDT[tl * 16 + dl] = v;
                }
        }
        __syncthreads();

        // ---- serial scan ----
        const __half* fXC = sXC + buf * 1024;
        const float*  fBC = sBC + buf * 2048;
#pragma unroll 4
        for (int t = 0; t < SW; t++) {
            float dtv = sDT[t * 16 + dloc];
            float xv  = __half2float(fXC[t * 16 + dloc]);
            float B1  = fBC[t * 32 + s];
            float B2  = fBC[t * 32 + 8 + s];
            float C1  = fBC[t * 32 + 16 + s];
            float C2  = fBC[t * 32 + 24 + s];
            float dA1 = __expf(dtv * A1);
            float dA2 = __expf(dtv * A2);
            float dbx = dtv * xv;
            h1 = fmaf(dA1, h1, dbx * B1);
            h2 = fmaf(dA2, h2, dbx * B2);
            float p = fmaf(h2, C2, h1 * C1);
            p += __shfl_xor_sync(0xffffffffu, p, 4);
            p += __shfl_xor_sync(0xffffffffu, p, 2);
            p += __shfl_xor_sync(0xffffffffu, p, 1);
            if (s == 0) sY[t * 16 + dloc] = fmaf(Dd, xv, p);
        }
        __syncthreads();

        // ---- gated writeback ----
        const __half* fZ = sZ + buf * 1024;
        int t0 = w * SW;
#pragma unroll
        for (int k = 0; k < 8; k++) {
            int idx = tid + k * 128;
            int t = idx >> 4, dd = idx & 15;
            float yv = sY[t * 16 + dd];
            float zv = __half2float(fZ[t * 16 + dd]);
            float sig = 1.f / (1.f + __expf(-zv));
            yv *= zv * sig;
            e_y[(size_t)(b * TT + t0 + t) * DIN + d0 + dd] = __float2half_rn(yv);
        }
        __syncthreads();
        buf ^= 1;
    }
}

// ==================== launch ====================
extern "C" void kernel_launch(void* const* d_in, const int* in_sizes, int n_in,
                              void* d_out, int out_size) {
    const float* x          = (const float*)d_in[0];
    const float* norm_w     = (const float*)d_in[1];
    const float* norm_b     = (const float*)d_in[2];
    const float* in_proj_w  = (const float*)d_in[3];
    const float* conv_w     = (const float*)d_in[4];
    const float* conv_b     = (const float*)d_in[5];
    const float* x_proj_w   = (const float*)d_in[6];
    const float* dt_proj_w  = (const float*)d_in[7];
    const float* dt_proj_b  = (const float*)d_in[8];
    const float* A_log      = (const float*)d_in[9];
    const float* Dvec       = (const float*)d_in[10];
    const float* out_proj_w = (const float*)d_in[11];
    float* out = (float*)d_out;

    float *part;
    __half *exn, *ew1, *exz, *exc, *ew2, *ew3, *ey, *ew4;
    cudaGetSymbolAddress((void**)&part, g_part);
    cudaGetSymbolAddress((void**)&exn,  e_xn);
    cudaGetSymbolAddress((void**)&ew1,  e_w1);
    cudaGetSymbolAddress((void**)&exz,  e_xz);
    cudaGetSymbolAddress((void**)&exc,  e_xc);
    cudaGetSymbolAddress((void**)&ew2,  e_w2);
    cudaGetSymbolAddress((void**)&ew3,  e_w3);
    cudaGetSymbolAddress((void**)&ey,   e_y);
    cudaGetSymbolAddress((void**)&ew4,  e_w4);

    const int smem128 = 3 * (128 * 128 + 128 * 128);   // 98304
    cudaFuncSetAttribute(gemm_mma<4, 128>, cudaFuncAttributeMaxDynamicSharedMemorySize, smem128);
    cudaFuncSetAttribute(gemm_mma<3, 128>, cudaFuncAttributeMaxDynamicSharedMemorySize, smem128);
    cudaFuncSetAttribute(gemm_mma<2, 128>, cudaFuncAttributeMaxDynamicSharedMemorySize, smem128);
    cudaFuncSetAttribute(scan_kernel, cudaFuncAttributeMaxDynamicSharedMemorySize, SCAN_SMEM);

    // 1. fused weight converts + LayerNorm
    Cvt4 cv;
    cv.in0 = in_proj_w;  cv.out0 = ew1;
    cv.in1 = out_proj_w; cv.out1 = ew4;
    cv.in2 = x_proj_w;   cv.out2 = ew2;
    cv.in3 = dt_proj_w;  cv.out3 = ew3;
    int n0 = 2 * DIN * CC / 2, n1 = CC * DIN / 2, n2 = XDBL * DIN / 2, n3 = DIN * DTRANK / 2;
    cv.c0 = n0; cv.c1 = n0 + n1; cv.c2 = n0 + n1 + n2; cv.c3 = n0 + n1 + n2 + n3;
    int cvtBlocks = (cv.c3 + 255) / 256;
    cvt_ln_kernel<<<LN_BLOCKS + cvtBlocks, 256>>>(cv, x, norm_w, norm_b);
    // 2. in_proj -> e_xz fp16
    gemm_mma<4, 128><<<dim3((2 * DIN) / 128, TOKS / 128), 256, smem128>>>(
        exn, CC, ew1, CC, exz, 2 * DIN, TOKS, 2 * DIN, CC, nullptr);
    // 3. conv + SiLU
    conv_silu_kernel<<<(TOKS / 4) * DIN / 256, 256>>>(conv_w, conv_b);
    // 4. x_proj split-K, SPLITK=8 (PROFILED LAUNCH)
    gemm_mma<3, 128><<<dim3(1, TOKS / 128, SPLITK), 256, smem128>>>(
        exc, DIN, ew2, DIN, part, XDBL, TOKS, XDBL, DIN, nullptr);
    // 5. reduce partials -> g_xdbl + e_dtr
    reduce_part_kernel<<<(TOKS * XDBL + 255) / 256, 256>>>();
    // 6. scan v5 (fused dt_proj + scan + gate, 2 blocks/SM)
    scan_kernel<<<(BB * DIN) / 16, 128, SCAN_SMEM>>>(A_log, Dvec, dt_proj_b);
    // 7. out_proj + residual, transposed store
    gemm_mma<2, 128><<<dim3(CC / 128, TOKS / 128), 256, smem128>>>(
        ey, DIN, ew4, DIN, out, 0, TOKS, CC, DIN, x);
}